// round 7
// baseline (speedup 1.0000x reference)
#include <cuda_runtime.h>
#include <mma.h>
using namespace nvcuda;

#define M_NODES 1024
#define TJ 128
#define UP 132            // row stride (floats); 528 B, 16B-aligned
#define NTHREADS 256

__device__ float g_pe_i[M_NODES * 64];
__device__ float g_pe_jT[64 * M_NODES];   // transposed: [c][j]

__device__ __forceinline__ float silu_f(float v) {
    return __fdividef(v, 1.0f + __expf(-v));
}
__device__ __forceinline__ float tf32r(float v) {
    unsigned r; asm("cvt.rna.tf32.f32 %0, %1;" : "=r"(r) : "f"(v));
    return __uint_as_float(r);
}

__global__ void pe_kernel(const float* __restrict__ h, const float* __restrict__ We1) {
    int id = blockIdx.x * blockDim.x + threadIdx.x;
    int i = id >> 6, k = id & 63;
    const float* hr = h + i * 64;
    float a0 = 0.f, a1 = 0.f;
#pragma unroll 8
    for (int c = 0; c < 64; c++) {
        float hv = hr[c];
        a0 += hv * We1[c * 64 + k];
        a1 += hv * We1[(64 + c) * 64 + k];
    }
    g_pe_i[id] = a0;
    g_pe_jT[k * M_NODES + i] = a1;
}

// SMEM layout (float offsets)
#define OFF_W2    0                 // 4096
#define OFF_WX1   4096              // 4096
#define OFF_BA2   8192              // 512 bias panel (col-major ld 64)
#define OFF_BAX   8704              // 512
#define OFF_ONES  9216              // 128
#define OFF_UT    9344              // 64*132 = 8448 (u / v scratch; redm,redx after loop)
#define OFF_MT    17792             // 8448
#define OFF_VEC   26240             // peib,w128,w129,wx2,be2 = 320
#define OFF_GEO   26560             // 2*640 (mis/gs reuse at end)
#define OFF_SELF  27840             // u_self 64 + m_self 64
#define OFF_REDXP 27968             // 4*132 = 528
#define SMEM_FLOATS 28496
#define SMEM_BYTES (SMEM_FLOATS * 4)

// 64k x 128j GEMM: dst = silu(W^T @ src + b). Warp w: kw=(w&3)*16, jw=(w>>2)*64.
// MI: warp-local row-sum of its own dst region -> miacc (no block sync needed).
// XP: warp-local wx2-weighted column partial of its own dst region -> redxp.
template<bool ROUND, bool MI, bool XP>
__device__ __forceinline__ void gemm_wmma(const float* __restrict__ Ws,
                                          const float* __restrict__ biasP,
                                          const float* __restrict__ ones,
                                          const float* __restrict__ src,
                                          float* __restrict__ dst,
                                          const float* __restrict__ wx2s,
                                          float* __restrict__ redxp,
                                          float& miacc,
                                          int kw, int jw, int lane)
{
    wmma::fragment<wmma::accumulator, 16, 16, 8, float> cf[4];
#pragma unroll
    for (int t = 0; t < 4; t++) wmma::fill_fragment(cf[t], 0.0f);
    wmma::fragment<wmma::matrix_a, 16, 16, 8, wmma::precision::tf32, wmma::col_major> af;
    wmma::fragment<wmma::matrix_b, 16, 16, 8, wmma::precision::tf32, wmma::row_major> bf;
#pragma unroll
    for (int c0 = 0; c0 < 64; c0 += 8) {
        wmma::load_matrix_sync(af, Ws + kw + c0 * 64, 64);
#pragma unroll
        for (int t = 0; t < 4; t++) {
            wmma::load_matrix_sync(bf, src + c0 * UP + jw + 16 * t, UP);
            wmma::mma_sync(cf[t], af, bf, cf[t]);
        }
    }
    wmma::load_matrix_sync(af, biasP + kw, 64);
    wmma::load_matrix_sync(bf, ones, 16);
#pragma unroll
    for (int t = 0; t < 4; t++) wmma::mma_sync(cf[t], af, bf, cf[t]);
#pragma unroll
    for (int t = 0; t < 4; t++) {
#pragma unroll
        for (int e = 0; e < cf[t].num_elements; e++) {
            float v = silu_f(cf[t].x[e]);
            cf[t].x[e] = ROUND ? tf32r(v) : v;
        }
        wmma::store_matrix_sync(dst + kw * UP + jw + 16 * t, cf[t], UP, wmma::mem_row_major);
    }
    if (MI) {
        // own region only: store_matrix_sync is warp-synchronous
        const float* p = dst + (kw + (lane >> 1)) * UP + jw + (lane & 1) * 32;
        float s = 0.f;
#pragma unroll
        for (int q = 0; q < 8; q++) {
            float4 v = *(const float4*)(p + 4 * q);
            s += (v.x + v.y) + (v.z + v.w);
        }
        miacc += s;
    }
    if (XP) {
        float sx = 0.f, sy = 0.f;
#pragma unroll
        for (int k = 0; k < 16; k++) {
            float wv = wx2s[kw + k];
            float2 v = *(const float2*)(dst + (kw + k) * UP + jw + lane * 2);
            sx += v.x * wv; sy += v.y * wv;
        }
        *(float2*)(redxp + (kw >> 4) * 132 + jw + lane * 2) = make_float2(sx, sy);
    }
}

__global__ void __launch_bounds__(NTHREADS, 2) egnn_main(
    const float* __restrict__ x, const float* __restrict__ a,
    const float* __restrict__ h,
    const float* __restrict__ We1, const float* __restrict__ be1,
    const float* __restrict__ We2, const float* __restrict__ be2,
    const float* __restrict__ Wx1, const float* __restrict__ bx1,
    const float* __restrict__ Wx2, const float* __restrict__ bx2,
    const float* __restrict__ Wh1, const float* __restrict__ bh1,
    const float* __restrict__ Wh2, const float* __restrict__ bh2,
    float* __restrict__ out)
{
    extern __shared__ float sm[];
    float* W2s   = sm + OFF_W2;
    float* Wx1s  = sm + OFF_WX1;
    float* bA2   = sm + OFF_BA2;
    float* bAX   = sm + OFF_BAX;
    float* ones  = sm + OFF_ONES;
    float* uT    = sm + OFF_UT;
    float* mT    = sm + OFF_MT;
    float* peib  = sm + OFF_VEC;
    float* w128s = peib + 64;
    float* w129s = w128s + 64;
    float* wx2s  = w129s + 64;
    float* be2s  = wx2s + 64;
    float* u_self = sm + OFF_SELF;
    float* m_self = u_self + 64;
    float* redxp  = sm + OFF_REDXP;

    const int tid = threadIdx.x;
    const int i = blockIdx.x;
    const int lane = tid & 31;

    for (int e = tid; e < 4096; e += NTHREADS) {
        W2s[e]  = tf32r(We2[e]);
        Wx1s[e] = tf32r(Wx1[e]);
    }
    for (int e = tid; e < 512; e += NTHREADS) {
        int kk = e >> 6, m = e & 63;
        bA2[e] = (kk == 0) ? tf32r(be2[m]) : 0.f;
        bAX[e] = (kk == 0) ? tf32r(bx1[m]) : 0.f;
    }
    if (tid < 128) ones[tid] = (tid < 16) ? 1.0f : 0.0f;
    if (tid < 64) {
        peib[tid]  = g_pe_i[i * 64 + tid] + be1[tid];
        w128s[tid] = We1[128 * 64 + tid];
        w129s[tid] = We1[129 * 64 + tid];
        wx2s[tid]  = Wx2[tid];
        be2s[tid]  = be2[tid];
    }
    const float xi0 = x[i * 3 + 0], xi1 = x[i * 3 + 1], xi2 = x[i * 3 + 2];
    const float bx2v = bx2[0];

    if (tid < 128) {
        float* g0 = sm + OFF_GEO;
        float xj0 = x[tid * 3 + 0], xj1 = x[tid * 3 + 1], xj2 = x[tid * 3 + 2];
        float dx = xi0 - xj0, dy = xi1 - xj1, dz = xi2 - xj2;
        g0[256 + tid] = dx; g0[384 + tid] = dy; g0[512 + tid] = dz;
        g0[tid] = dx * dx + dy * dy + dz * dz;
        g0[128 + tid] = a[i * M_NODES + tid];
    }
    __syncthreads();

    // self-edge m (diagonal correction for m_i): d2=0, a=a_ii
    if (tid < 64) {
        float a_ii = a[i * M_NODES + i];
        float pre = peib[tid] + g_pe_jT[tid * M_NODES + i] + a_ii * w129s[tid];
        u_self[tid] = tf32r(silu_f(pre));
    }
    __syncthreads();
    if (tid < 64) {
        float accd = be2s[tid];
#pragma unroll 8
        for (int c = 0; c < 64; c++) accd += u_self[c] * W2s[c * 64 + tid];
        m_self[tid] = silu_f(accd);
    }

    const int w  = tid >> 5;
    const int kw = (w & 3) * 16;
    const int jw = (w >> 2) * 64;
    float miacc = 0.f;
    float ax = 0.f, ay = 0.f, az = 0.f;

    for (int t = 0; t < 8; t++) {
        const int j0 = t * TJ;
        float* geo = sm + OFF_GEO + (t & 1) * 640;
        float* d2s = geo, *a_s = geo + 128;

        // finalize x-accumulation for previous tile (overlaps phase A; geo(t-1)
        // buffer == geo(t+1) buffer but its prefetch happens after the next sync)
        if (t > 0 && tid < 128) {
            float* gp = sm + OFF_GEO + ((t - 1) & 1) * 640;
            float s = bx2v + redxp[tid] + redxp[132 + tid]
                           + redxp[264 + tid] + redxp[396 + tid];
            ax += gp[256 + tid] * s; ay += gp[384 + tid] * s; az += gp[512 + tid] * s;
        }

        // ---- phase A: uT[c][j] = tf32(silu(pre)) ----
        {
            const int jq = (tid & 31) * 4;
#pragma unroll
            for (int p = 0; p < 8; p++) {
                int c = p * 8 + w;
                float4 pj = *(const float4*)&g_pe_jT[c * M_NODES + j0 + jq];
                float pc = peib[c], wa = w128s[c], wb = w129s[c];
                float4 dd = *(const float4*)&d2s[jq];
                float4 aa = *(const float4*)&a_s[jq];
                float4 r;
                r.x = tf32r(silu_f(pc + pj.x + dd.x * wa + aa.x * wb));
                r.y = tf32r(silu_f(pc + pj.y + dd.y * wa + aa.y * wb));
                r.z = tf32r(silu_f(pc + pj.z + dd.z * wa + aa.z * wb));
                r.w = tf32r(silu_f(pc + pj.w + dd.w * wa + aa.w * wb));
                *(float4*)&uT[c * UP + jq] = r;
            }
        }
        __syncthreads();

        float px0 = 0.f, px1 = 0.f, px2 = 0.f, pa = 0.f;
        const bool pf = (tid < 128) && (t + 1 < 8);
        if (pf) {
            int jn = (t + 1) * TJ + tid;
            px0 = x[jn * 3 + 0]; px1 = x[jn * 3 + 1]; px2 = x[jn * 3 + 2];
            pa = a[i * M_NODES + jn];
        }

        // ---- phase B: mT = tf32(silu(u @ We2 + be2)) + warp-local m_i partials ----
        gemm_wmma<true, true, false>(W2s, bA2, ones, uT, mT, wx2s, redxp, miacc, kw, jw, lane);

        if (pf) {
            float* gn = sm + OFF_GEO + ((t + 1) & 1) * 640;
            float dx = xi0 - px0, dy = xi1 - px1, dz = xi2 - px2;
            gn[256 + tid] = dx; gn[384 + tid] = dy; gn[512 + tid] = dz;
            gn[tid] = dx * dx + dy * dy + dz * dz;
            gn[128 + tid] = pa;
        }
        __syncthreads();

        // ---- phase C: v = silu(m @ Wx1 + bx1) (scratch uT) + warp-local wx2 dot ----
        gemm_wmma<false, false, true>(Wx1s, bAX, ones, mT, uT, wx2s, redxp, miacc, kw, jw, lane);
        __syncthreads();
    }

    // finalize x for tile 7
    if (tid < 128) {
        float* gp = sm + OFF_GEO + (7 & 1) * 640;
        float s = bx2v + redxp[tid] + redxp[132 + tid]
                       + redxp[264 + tid] + redxp[396 + tid];
        ax += gp[256 + tid] * s; ay += gp[384 + tid] * s; az += gp[512 + tid] * s;
    }

    // ---- reductions (alias uT region, dead now) ----
    float* redm = sm + OFF_UT;            // 256: [k][4]
    float* redx = sm + OFF_UT + 256;      // 384
    redm[(kw + (lane >> 1)) * 4 + (jw >> 5) + (lane & 1)] = miacc;
    if (tid < 128) { redx[tid] = ax; redx[128 + tid] = ay; redx[256 + tid] = az; }
    __syncthreads();

    float* mis = sm + OFF_GEO;
    float* gs  = sm + OFF_GEO + 64;
    if (tid < 64) {
        mis[tid] = (redm[tid * 4] + redm[tid * 4 + 1])
                 + (redm[tid * 4 + 2] + redm[tid * 4 + 3]) - m_self[tid];
    }
    if (tid >= 128 && tid < 131) {
        int comp = tid - 128;
        float s = 0.f;
        for (int q = 0; q < 128; q++) s += redx[comp * 128 + q];
        const float C = 1.0f / (float)(M_NODES - 1);
        out[i * 3 + comp] = x[i * 3 + comp] + C * s;
    }
    __syncthreads();

    // ---- phi_h ----
    if (tid < 64) {
        float acc = bh1[tid];
        const float* hr = h + i * 64;
#pragma unroll 4
        for (int c = 0; c < 64; c++) acc += hr[c] * Wh1[c * 64 + tid];
#pragma unroll 4
        for (int c = 0; c < 64; c++) acc += mis[c] * Wh1[(64 + c) * 64 + tid];
        gs[tid] = silu_f(acc);
    }
    __syncthreads();
    if (tid < 64) {
        float acc = bh2[tid];
#pragma unroll 4
        for (int c = 0; c < 64; c++) acc += gs[c] * Wh2[c * 64 + tid];
        out[3 * M_NODES + i * 64 + tid] = acc;
    }
}

extern "C" void kernel_launch(void* const* d_in, const int* in_sizes, int n_in,
                              void* d_out, int out_size) {
    const float* x   = (const float*)d_in[0];
    const float* a   = (const float*)d_in[1];
    const float* h   = (const float*)d_in[2];
    const float* We1 = (const float*)d_in[3];
    const float* be1 = (const float*)d_in[4];
    const float* We2 = (const float*)d_in[5];
    const float* be2 = (const float*)d_in[6];
    const float* Wx1 = (const float*)d_in[7];
    const float* bx1 = (const float*)d_in[8];
    const float* Wx2 = (const float*)d_in[9];
    const float* bx2 = (const float*)d_in[10];
    const float* Wh1 = (const float*)d_in[11];
    const float* bh1 = (const float*)d_in[12];
    const float* Wh2 = (const float*)d_in[13];
    const float* bh2 = (const float*)d_in[14];
    float* out = (float*)d_out;

    cudaFuncSetAttribute(egnn_main, cudaFuncAttributeMaxDynamicSharedMemorySize, SMEM_BYTES);

    pe_kernel<<<(M_NODES * 64) / NTHREADS, NTHREADS>>>(h, We1);
    egnn_main<<<M_NODES, NTHREADS, SMEM_BYTES>>>(
        x, a, h, We1, be1, We2, be2, Wx1, bx1, Wx2, bx2,
        Wh1, bh1, Wh2, bh2, out);
}

// round 8
// speedup vs baseline: 1.5516x; 1.5516x over previous
#include <cuda_runtime.h>
#include <cuda_fp16.h>
#include <mma.h>
using namespace nvcuda;

#define M_NODES 1024
#define UPH 136           // half-row stride for uA/mT (136*2=272B, mult of 16B)
#define STLD 20           // stage row stride (floats)
#define NTHREADS 256

__device__ float g_pe_i[M_NODES * 64];
__device__ float g_pe_jT[64 * M_NODES];   // transposed: [c][j]

__device__ __forceinline__ float silu_f(float v) {
    return __fdividef(v, 1.0f + __expf(-v));
}

__global__ void pe_kernel(const float* __restrict__ h, const float* __restrict__ We1) {
    int id = blockIdx.x * blockDim.x + threadIdx.x;
    int i = id >> 6, k = id & 63;
    const float* hr = h + i * 64;
    float a0 = 0.f, a1 = 0.f;
#pragma unroll 8
    for (int c = 0; c < 64; c++) {
        float hv = hr[c];
        a0 += hv * We1[c * 64 + k];
        a1 += hv * We1[(64 + c) * 64 + k];
    }
    g_pe_i[id] = a0;
    g_pe_jT[k * M_NODES + i] = a1;
}

// SMEM layout (float offsets)
#define OFF_W2H   0         // 4096 halfs = 2048 fl
#define OFF_WX1H  2048      // 2048 fl
#define OFF_UA0   4096      // 64*136 halfs = 4352 fl
#define OFF_UA1   8448      // 4352 fl
#define OFF_MTH   12800     // 4352 fl
#define OFF_STAGE 17152     // 8 warps * 320 = 2560 fl  (redm/redx alias post-loop)
#define OFF_VEC   19712     // peib,w128,w129,wx2,be2,bx1 = 384
#define OFF_GEOA  20096     // 2 * 256 (d2 128 + a 128)   (mis/gs alias post-loop)
#define OFF_REDXP 20608     // 4*132 = 528
#define OFF_SELF  21136     // u_self 64 + m_self 64
#define SMEM_FLOATS 21264
#define SMEM_BYTES (SMEM_FLOATS * 4)

// GEMM B: mT = fp16(silu(W2^T @ u + be2)); accumulates m_i partials per lane.
__device__ __forceinline__ void gemmB(const __half* __restrict__ W2h,
                                      const __half* __restrict__ uAh,
                                      __half* __restrict__ mTh,
                                      const float* __restrict__ be2s,
                                      float* __restrict__ stage_w,
                                      float& miacc, int kw, int jw, int lane)
{
    wmma::fragment<wmma::accumulator, 16, 16, 16, float> cf[4];
#pragma unroll
    for (int t = 0; t < 4; t++) wmma::fill_fragment(cf[t], 0.0f);
    wmma::fragment<wmma::matrix_a, 16, 16, 16, __half, wmma::col_major> af;
    wmma::fragment<wmma::matrix_b, 16, 16, 16, __half, wmma::row_major> bf;
#pragma unroll
    for (int c0 = 0; c0 < 64; c0 += 16) {
        wmma::load_matrix_sync(af, W2h + kw + c0 * 64, 64);
#pragma unroll
        for (int t = 0; t < 4; t++) {
            wmma::load_matrix_sync(bf, uAh + c0 * UPH + jw + 16 * t, UPH);
            wmma::mma_sync(cf[t], af, bf, cf[t]);
        }
    }
    const int kl = lane >> 1;
    const int jh = (lane & 1) * 8;
    const float bias = be2s[kw + kl];
#pragma unroll
    for (int t = 0; t < 4; t++) {
        wmma::store_matrix_sync(stage_w, cf[t], STLD, wmma::mem_row_major);
        __syncwarp();
        float4 v0 = *(const float4*)(stage_w + kl * STLD + jh);
        float4 v1 = *(const float4*)(stage_w + kl * STLD + jh + 4);
        float f[8] = {v0.x, v0.y, v0.z, v0.w, v1.x, v1.y, v1.z, v1.w};
        __half hh[8];
#pragma unroll
        for (int q = 0; q < 8; q++) {
            float m = silu_f(f[q] + bias);
            miacc += m;
            hh[q] = __float2half_rn(m);
        }
        *(uint4*)(mTh + (kw + kl) * UPH + jw + 16 * t + jh) = *(uint4*)hh;
        __syncwarp();
    }
}

// GEMM C: z = Wx1^T @ m; per j: s_j += sum_k silu(z+bx1)*wx2 -> redxp slice.
__device__ __forceinline__ void gemmC(const __half* __restrict__ Wx1h,
                                      const __half* __restrict__ mTh,
                                      const float* __restrict__ bx1s,
                                      const float* __restrict__ wx2s,
                                      float* __restrict__ redxp,
                                      float* __restrict__ stage_w,
                                      int kw, int jw, int lane)
{
    wmma::fragment<wmma::accumulator, 16, 16, 16, float> cf[4];
#pragma unroll
    for (int t = 0; t < 4; t++) wmma::fill_fragment(cf[t], 0.0f);
    wmma::fragment<wmma::matrix_a, 16, 16, 16, __half, wmma::col_major> af;
    wmma::fragment<wmma::matrix_b, 16, 16, 16, __half, wmma::row_major> bf;
#pragma unroll
    for (int c0 = 0; c0 < 64; c0 += 16) {
        wmma::load_matrix_sync(af, Wx1h + kw + c0 * 64, 64);
#pragma unroll
        for (int t = 0; t < 4; t++) {
            wmma::load_matrix_sync(bf, mTh + c0 * UPH + jw + 16 * t, UPH);
            wmma::mma_sync(cf[t], af, bf, cf[t]);
        }
    }
    const int jl = lane & 15;
    const int khalf = lane >> 4;
#pragma unroll
    for (int t = 0; t < 4; t++) {
        wmma::store_matrix_sync(stage_w, cf[t], STLD, wmma::mem_row_major);
        __syncwarp();
        float s = 0.f;
#pragma unroll
        for (int q = 0; q < 8; q++) {
            int k2 = khalf * 8 + q;
            float z = stage_w[k2 * STLD + jl] + bx1s[kw + k2];
            s += silu_f(z) * wx2s[kw + k2];
        }
        s += __shfl_xor_sync(0xffffffff, s, 16);
        if (lane < 16) redxp[(kw >> 4) * 132 + jw + 16 * t + jl] = s;
        __syncwarp();
    }
}

__global__ void __launch_bounds__(NTHREADS, 2) egnn_main(
    const float* __restrict__ x, const float* __restrict__ a,
    const float* __restrict__ h,
    const float* __restrict__ We1, const float* __restrict__ be1,
    const float* __restrict__ We2, const float* __restrict__ be2,
    const float* __restrict__ Wx1, const float* __restrict__ bx1,
    const float* __restrict__ Wx2, const float* __restrict__ bx2,
    const float* __restrict__ Wh1, const float* __restrict__ bh1,
    const float* __restrict__ Wh2, const float* __restrict__ bh2,
    float* __restrict__ out)
{
    extern __shared__ float sm[];
    __half* W2h  = (__half*)(sm + OFF_W2H);
    __half* Wx1h = (__half*)(sm + OFF_WX1H);
    __half* uA0h = (__half*)(sm + OFF_UA0);
    __half* uA1h = (__half*)(sm + OFF_UA1);
    __half* mTh  = (__half*)(sm + OFF_MTH);
    float* stage = sm + OFF_STAGE;
    float* peib  = sm + OFF_VEC;
    float* w128s = peib + 64;
    float* w129s = w128s + 64;
    float* wx2s  = w129s + 64;
    float* be2s  = wx2s + 64;
    float* bx1s  = be2s + 64;
    float* redxp = sm + OFF_REDXP;
    float* u_self = sm + OFF_SELF;
    float* m_self = u_self + 64;

    const int tid = threadIdx.x;
    const int i = blockIdx.x;
    const int lane = tid & 31;
    const int w = tid >> 5;
    const int kw = (w & 3) * 16;
    const int jw = (w >> 2) * 64;
    float* stage_w = stage + w * 320;

    for (int e = tid; e < 4096; e += NTHREADS) {
        W2h[e]  = __float2half_rn(We2[e]);
        Wx1h[e] = __float2half_rn(Wx1[e]);
    }
    if (tid < 64) {
        peib[tid]  = g_pe_i[i * 64 + tid] + be1[tid];
        w128s[tid] = We1[128 * 64 + tid];
        w129s[tid] = We1[129 * 64 + tid];
        wx2s[tid]  = Wx2[tid];
        be2s[tid]  = be2[tid];
        bx1s[tid]  = bx1[tid];
    }
    const float xi0 = x[i * 3 + 0], xi1 = x[i * 3 + 1], xi2 = x[i * 3 + 2];
    const float bx2v = bx2[0];

    // geoA[0] for tile 0
    if (tid < 128) {
        float* g0 = sm + OFF_GEOA;
        float dx = xi0 - x[tid * 3 + 0];
        float dy = xi1 - x[tid * 3 + 1];
        float dz = xi2 - x[tid * 3 + 2];
        g0[tid] = dx * dx + dy * dy + dz * dz;
        g0[128 + tid] = a[i * M_NODES + tid];
    }
    __syncthreads();

    // u_self (fp16-rounded, stored as float) + phase A for tile 0
    if (tid < 64) {
        float a_ii = a[i * M_NODES + i];
        float pre = peib[tid] + g_pe_jT[tid * M_NODES + i] + a_ii * w129s[tid];
        u_self[tid] = __half2float(__float2half_rn(silu_f(pre)));
    }
    {
        const float* geoA = sm + OFF_GEOA;
        const int jq = lane * 4;
#pragma unroll
        for (int p = 0; p < 8; p++) {
            int c = p * 8 + w;
            float4 pj = *(const float4*)&g_pe_jT[c * M_NODES + jq];
            float pc = peib[c], wa = w128s[c], wb = w129s[c];
            float4 dd = *(const float4*)&geoA[jq];
            float4 aa = *(const float4*)&geoA[128 + jq];
            __half hh[4];
            hh[0] = __float2half_rn(silu_f(pc + pj.x + dd.x * wa + aa.x * wb));
            hh[1] = __float2half_rn(silu_f(pc + pj.y + dd.y * wa + aa.y * wb));
            hh[2] = __float2half_rn(silu_f(pc + pj.z + dd.z * wa + aa.z * wb));
            hh[3] = __float2half_rn(silu_f(pc + pj.w + dd.w * wa + aa.w * wb));
            *(uint2*)(uA0h + c * UPH + jq) = *(uint2*)hh;
        }
    }
    __syncthreads();

    float miacc = 0.f;
    float ax = 0.f, ay = 0.f, az = 0.f;

    for (int t = 0; t < 8; t++) {
        __half* uCur  = (t & 1) ? uA1h : uA0h;
        __half* uNext = (t & 1) ? uA0h : uA1h;

        // ======== Phase P1: GEMM B (+ m_self, x-accum(t-1), geo prefetch) ========
        const bool pf = (tid < 128) && (t + 1 < 8);
        float pd2 = 0.f, pa = 0.f;
        if (pf) {
            int jn = (t + 1) * 128 + tid;
            float dx = xi0 - x[jn * 3 + 0];
            float dy = xi1 - x[jn * 3 + 1];
            float dz = xi2 - x[jn * 3 + 2];
            pd2 = dx * dx + dy * dy + dz * dz;
            pa = a[i * M_NODES + jn];
        }
        if (t == 0 && tid < 64) {
            float accd = be2s[tid];
#pragma unroll 8
            for (int c = 0; c < 64; c++)
                accd += u_self[c] * __half2float(W2h[tid + c * 64]);
            m_self[tid] = silu_f(accd);
        }
        if (t > 0 && tid < 128) {
            int jg = (t - 1) * 128 + tid;
            float s = bx2v + redxp[tid] + redxp[132 + tid]
                           + redxp[264 + tid] + redxp[396 + tid];
            float dx = xi0 - x[jg * 3 + 0];
            float dy = xi1 - x[jg * 3 + 1];
            float dz = xi2 - x[jg * 3 + 2];
            ax += dx * s; ay += dy * s; az += dz * s;
        }

        gemmB(W2h, uCur, mTh, be2s, stage_w, miacc, kw, jw, lane);

        if (pf) {
            float* gn = sm + OFF_GEOA + ((t + 1) & 1) * 256;
            gn[tid] = pd2;
            gn[128 + tid] = pa;
        }
        __syncthreads();

        // ======== Phase P2: GEMM C + phase A(t+1) ========
        gemmC(Wx1h, mTh, bx1s, wx2s, redxp, stage_w, kw, jw, lane);

        if (t + 1 < 8) {
            const float* geoA = sm + OFF_GEOA + ((t + 1) & 1) * 256;
            const int j0 = (t + 1) * 128;
            const int jq = lane * 4;
#pragma unroll
            for (int p = 0; p < 8; p++) {
                int c = p * 8 + w;
                float4 pj = *(const float4*)&g_pe_jT[c * M_NODES + j0 + jq];
                float pc = peib[c], wa = w128s[c], wb = w129s[c];
                float4 dd = *(const float4*)&geoA[jq];
                float4 aa = *(const float4*)&geoA[128 + jq];
                __half hh[4];
                hh[0] = __float2half_rn(silu_f(pc + pj.x + dd.x * wa + aa.x * wb));
                hh[1] = __float2half_rn(silu_f(pc + pj.y + dd.y * wa + aa.y * wb));
                hh[2] = __float2half_rn(silu_f(pc + pj.z + dd.z * wa + aa.z * wb));
                hh[3] = __float2half_rn(silu_f(pc + pj.w + dd.w * wa + aa.w * wb));
                *(uint2*)(uNext + c * UPH + jq) = *(uint2*)hh;
            }
        }
        __syncthreads();
    }

    // x-accum for tile 7
    if (tid < 128) {
        int jg = 7 * 128 + tid;
        float s = bx2v + redxp[tid] + redxp[132 + tid]
                       + redxp[264 + tid] + redxp[396 + tid];
        float dx = xi0 - x[jg * 3 + 0];
        float dy = xi1 - x[jg * 3 + 1];
        float dz = xi2 - x[jg * 3 + 2];
        ax += dx * s; ay += dy * s; az += dz * s;
    }

    // reductions (alias stage: dead now)
    float* redm = sm + OFF_STAGE;         // [64][4]
    float* redx = sm + OFF_STAGE + 256;   // 384
    redm[(kw + (lane >> 1)) * 4 + (jw >> 6) * 2 + (lane & 1)] = miacc;
    if (tid < 128) { redx[tid] = ax; redx[128 + tid] = ay; redx[256 + tid] = az; }
    __syncthreads();

    float* mis = sm + OFF_GEOA;
    float* gs  = sm + OFF_GEOA + 64;
    if (tid < 64) {
        mis[tid] = (redm[tid * 4] + redm[tid * 4 + 1])
                 + (redm[tid * 4 + 2] + redm[tid * 4 + 3]) - m_self[tid];
    }
    if (tid >= 128 && tid < 131) {
        int comp = tid - 128;
        float s = 0.f;
        for (int q = 0; q < 128; q++) s += redx[comp * 128 + q];
        const float C = 1.0f / (float)(M_NODES - 1);
        out[i * 3 + comp] = x[i * 3 + comp] + C * s;
    }
    __syncthreads();

    // phi_h
    if (tid < 64) {
        float acc = bh1[tid];
        const float* hr = h + i * 64;
#pragma unroll 4
        for (int c = 0; c < 64; c++) acc += hr[c] * Wh1[c * 64 + tid];
#pragma unroll 4
        for (int c = 0; c < 64; c++) acc += mis[c] * Wh1[(64 + c) * 64 + tid];
        gs[tid] = silu_f(acc);
    }
    __syncthreads();
    if (tid < 64) {
        float acc = bh2[tid];
#pragma unroll 4
        for (int c = 0; c < 64; c++) acc += gs[c] * Wh2[c * 64 + tid];
        out[3 * M_NODES + i * 64 + tid] = acc;
    }
}

extern "C" void kernel_launch(void* const* d_in, const int* in_sizes, int n_in,
                              void* d_out, int out_size) {
    const float* x   = (const float*)d_in[0];
    const float* a   = (const float*)d_in[1];
    const float* h   = (const float*)d_in[2];
    const float* We1 = (const float*)d_in[3];
    const float* be1 = (const float*)d_in[4];
    const float* We2 = (const float*)d_in[5];
    const float* be2 = (const float*)d_in[6];
    const float* Wx1 = (const float*)d_in[7];
    const float* bx1 = (const float*)d_in[8];
    const float* Wx2 = (const float*)d_in[9];
    const float* bx2 = (const float*)d_in[10];
    const float* Wh1 = (const float*)d_in[11];
    const float* bh1 = (const float*)d_in[12];
    const float* Wh2 = (const float*)d_in[13];
    const float* bh2 = (const float*)d_in[14];
    float* out = (float*)d_out;

    cudaFuncSetAttribute(egnn_main, cudaFuncAttributeMaxDynamicSharedMemorySize, SMEM_BYTES);

    pe_kernel<<<(M_NODES * 64) / NTHREADS, NTHREADS>>>(h, We1);
    egnn_main<<<M_NODES, NTHREADS, SMEM_BYTES>>>(
        x, a, h, We1, be1, We2, be2, Wx1, bx1, Wx2, bx2,
        Wh1, bh1, Wh2, bh2, out);
}

// round 9
// speedup vs baseline: 1.9672x; 1.2678x over previous
#include <cuda_runtime.h>
#include <cuda_fp16.h>
#include <mma.h>
using namespace nvcuda;

#define M_NODES 1024
#define UPH 136           // half-row stride for uA/mT (272B, mult of 16B)
#define NTHREADS 256

__device__ float g_pe_i[M_NODES * 64];
__device__ float g_pe_jT[64 * M_NODES];   // transposed: [c][j]

__device__ __forceinline__ float silu_f(float v) {
    return __fdividef(v, 1.0f + __expf(-v));
}

__global__ void pe_kernel(const float* __restrict__ h, const float* __restrict__ We1) {
    int id = blockIdx.x * blockDim.x + threadIdx.x;
    int i = id >> 6, k = id & 63;
    const float* hr = h + i * 64;
    float a0 = 0.f, a1 = 0.f;
#pragma unroll 8
    for (int c = 0; c < 64; c++) {
        float hv = hr[c];
        a0 += hv * We1[c * 64 + k];
        a1 += hv * We1[(64 + c) * 64 + k];
    }
    g_pe_i[id] = a0;
    g_pe_jT[k * M_NODES + i] = a1;
}

// SMEM layout (float offsets)
#define OFF_W2H   0         // 2048
#define OFF_WX1H  2048      // 2048
#define OFF_UA0   4096      // 4352
#define OFF_UA1   8448      // 4352
#define OFF_MTH   12800     // 4352
#define OFF_VEC   17152     // peib,w128,w129,wx2,be2,bx1 = 384
#define OFF_GEOA  17536     // 2*256 (d2+a)  (mis/gs alias at end)
#define OFF_REDXP 18048     // 4*132 = 528
#define OFF_SELF  18576     // u_self 64 + m_self 64
#define OFF_RED   18704     // redm 128 + redx 384
#define SMEM_FLOATS 19216
#define SMEM_BYTES (SMEM_FLOATS * 4)

// HMMA m16n16k16 fp32 accumulator mapping (sm_80+):
//   lane L: q=L>>2, p=L&3; element e: row = q + ((e&2)?8:0), col = 2p + (e&1) + ((e>=4)?8:0)

// GEMM B: mT = fp16(silu(W2^T @ u + be2)); per-row m_i partials in mi0 (row q), mi1 (row q+8).
__device__ __forceinline__ void gemmB(const __half* __restrict__ W2h,
                                      const __half* __restrict__ uAh,
                                      __half* __restrict__ mTh,
                                      const float* __restrict__ be2s,
                                      float& mi0, float& mi1,
                                      int kw, int jw, int lane)
{
    wmma::fragment<wmma::accumulator, 16, 16, 16, float> cf[4];
#pragma unroll
    for (int t = 0; t < 4; t++) wmma::fill_fragment(cf[t], 0.0f);
    wmma::fragment<wmma::matrix_a, 16, 16, 16, __half, wmma::col_major> af;
    wmma::fragment<wmma::matrix_b, 16, 16, 16, __half, wmma::row_major> bf;
#pragma unroll
    for (int c0 = 0; c0 < 64; c0 += 16) {
        wmma::load_matrix_sync(af, W2h + kw + c0 * 64, 64);
#pragma unroll
        for (int t = 0; t < 4; t++) {
            wmma::load_matrix_sync(bf, uAh + c0 * UPH + jw + 16 * t, UPH);
            wmma::mma_sync(cf[t], af, bf, cf[t]);
        }
    }
    const int q = lane >> 2, p = lane & 3;
    const int r0 = kw + q, r1 = r0 + 8;
    const float b0 = be2s[r0], b1 = be2s[r1];
#pragma unroll
    for (int t = 0; t < 4; t++) {
        float m0 = silu_f(cf[t].x[0] + b0), m1 = silu_f(cf[t].x[1] + b0);
        float m2 = silu_f(cf[t].x[2] + b1), m3 = silu_f(cf[t].x[3] + b1);
        float m4 = silu_f(cf[t].x[4] + b0), m5 = silu_f(cf[t].x[5] + b0);
        float m6 = silu_f(cf[t].x[6] + b1), m7 = silu_f(cf[t].x[7] + b1);
        mi0 += (m0 + m1) + (m4 + m5);
        mi1 += (m2 + m3) + (m6 + m7);
        __half2* d0 = (__half2*)(mTh + r0 * UPH + jw + 16 * t + p * 2);
        __half2* d1 = (__half2*)(mTh + r1 * UPH + jw + 16 * t + p * 2);
        d0[0] = __floats2half2_rn(m0, m1);
        d0[4] = __floats2half2_rn(m4, m5);
        d1[0] = __floats2half2_rn(m2, m3);
        d1[4] = __floats2half2_rn(m6, m7);
    }
}

// GEMM C: z = Wx1^T @ m; column-reduce silu(z+bx1)*wx2 over 16 k-rows -> redxp slice.
__device__ __forceinline__ void gemmC(const __half* __restrict__ Wx1h,
                                      const __half* __restrict__ mTh,
                                      const float* __restrict__ bx1s,
                                      const float* __restrict__ wx2s,
                                      float* __restrict__ redxp,
                                      int kw, int jw, int lane)
{
    wmma::fragment<wmma::accumulator, 16, 16, 16, float> cf[4];
#pragma unroll
    for (int t = 0; t < 4; t++) wmma::fill_fragment(cf[t], 0.0f);
    wmma::fragment<wmma::matrix_a, 16, 16, 16, __half, wmma::col_major> af;
    wmma::fragment<wmma::matrix_b, 16, 16, 16, __half, wmma::row_major> bf;
#pragma unroll
    for (int c0 = 0; c0 < 64; c0 += 16) {
        wmma::load_matrix_sync(af, Wx1h + kw + c0 * 64, 64);
#pragma unroll
        for (int t = 0; t < 4; t++) {
            wmma::load_matrix_sync(bf, mTh + c0 * UPH + jw + 16 * t, UPH);
            wmma::mma_sync(cf[t], af, bf, cf[t]);
        }
    }
    const int q = lane >> 2, p = lane & 3;
    const int r0 = kw + q, r1 = r0 + 8;
    const float ba = bx1s[r0], bb = bx1s[r1];
    const float wa = wx2s[r0], wb = wx2s[r1];
#pragma unroll
    for (int t = 0; t < 4; t++) {
        float s0 = silu_f(cf[t].x[0] + ba) * wa + silu_f(cf[t].x[2] + bb) * wb;
        float s1 = silu_f(cf[t].x[1] + ba) * wa + silu_f(cf[t].x[3] + bb) * wb;
        float s2 = silu_f(cf[t].x[4] + ba) * wa + silu_f(cf[t].x[6] + bb) * wb;
        float s3 = silu_f(cf[t].x[5] + ba) * wa + silu_f(cf[t].x[7] + bb) * wb;
#pragma unroll
        for (int msk = 4; msk <= 16; msk <<= 1) {
            s0 += __shfl_xor_sync(0xffffffff, s0, msk);
            s1 += __shfl_xor_sync(0xffffffff, s1, msk);
            s2 += __shfl_xor_sync(0xffffffff, s2, msk);
            s3 += __shfl_xor_sync(0xffffffff, s3, msk);
        }
        if (lane < 4) {
            float* rp = redxp + (kw >> 4) * 132 + jw + 16 * t + p * 2;
            *(float2*)rp       = make_float2(s0, s1);
            *(float2*)(rp + 8) = make_float2(s2, s3);
        }
    }
}

__global__ void __launch_bounds__(NTHREADS, 2) egnn_main(
    const float* __restrict__ x, const float* __restrict__ a,
    const float* __restrict__ h,
    const float* __restrict__ We1, const float* __restrict__ be1,
    const float* __restrict__ We2, const float* __restrict__ be2,
    const float* __restrict__ Wx1, const float* __restrict__ bx1,
    const float* __restrict__ Wx2, const float* __restrict__ bx2,
    const float* __restrict__ Wh1, const float* __restrict__ bh1,
    const float* __restrict__ Wh2, const float* __restrict__ bh2,
    float* __restrict__ out)
{
    extern __shared__ float sm[];
    __half* W2h  = (__half*)(sm + OFF_W2H);
    __half* Wx1h = (__half*)(sm + OFF_WX1H);
    __half* uA0h = (__half*)(sm + OFF_UA0);
    __half* uA1h = (__half*)(sm + OFF_UA1);
    __half* mTh  = (__half*)(sm + OFF_MTH);
    float* peib  = sm + OFF_VEC;
    float* w128s = peib + 64;
    float* w129s = w128s + 64;
    float* wx2s  = w129s + 64;
    float* be2s  = wx2s + 64;
    float* bx1s  = be2s + 64;
    float* redxp = sm + OFF_REDXP;
    float* u_self = sm + OFF_SELF;
    float* m_self = u_self + 64;

    const int tid = threadIdx.x;
    const int i = blockIdx.x;
    const int lane = tid & 31;
    const int w = tid >> 5;
    const int kw = (w & 3) * 16;
    const int jw = (w >> 2) * 64;

    for (int e = tid; e < 4096; e += NTHREADS) {
        W2h[e]  = __float2half_rn(We2[e]);
        Wx1h[e] = __float2half_rn(Wx1[e]);
    }
    if (tid < 64) {
        peib[tid]  = g_pe_i[i * 64 + tid] + be1[tid];
        w128s[tid] = We1[128 * 64 + tid];
        w129s[tid] = We1[129 * 64 + tid];
        wx2s[tid]  = Wx2[tid];
        be2s[tid]  = be2[tid];
        bx1s[tid]  = bx1[tid];
    }
    const float xi0 = x[i * 3 + 0], xi1 = x[i * 3 + 1], xi2 = x[i * 3 + 2];
    const float bx2v = bx2[0];

    // geoA[0] for tile 0
    if (tid < 128) {
        float* g0 = sm + OFF_GEOA;
        float dx = xi0 - x[tid * 3 + 0];
        float dy = xi1 - x[tid * 3 + 1];
        float dz = xi2 - x[tid * 3 + 2];
        g0[tid] = dx * dx + dy * dy + dz * dz;
        g0[128 + tid] = a[i * M_NODES + tid];
    }
    __syncthreads();

    // u_self (fp16-rounded) + phase A for tile 0
    if (tid < 64) {
        float a_ii = a[i * M_NODES + i];
        float pre = peib[tid] + g_pe_jT[tid * M_NODES + i] + a_ii * w129s[tid];
        u_self[tid] = __half2float(__float2half_rn(silu_f(pre)));
    }
    {
        const float* geoA = sm + OFF_GEOA;
        const int jq = lane * 4;
#pragma unroll
        for (int p = 0; p < 8; p++) {
            int c = p * 8 + w;
            float4 pj = *(const float4*)&g_pe_jT[c * M_NODES + jq];
            float pc = peib[c], wa = w128s[c], wb = w129s[c];
            float4 dd = *(const float4*)&geoA[jq];
            float4 aa = *(const float4*)&geoA[128 + jq];
            __half hh[4];
            hh[0] = __float2half_rn(silu_f(pc + pj.x + dd.x * wa + aa.x * wb));
            hh[1] = __float2half_rn(silu_f(pc + pj.y + dd.y * wa + aa.y * wb));
            hh[2] = __float2half_rn(silu_f(pc + pj.z + dd.z * wa + aa.z * wb));
            hh[3] = __float2half_rn(silu_f(pc + pj.w + dd.w * wa + aa.w * wb));
            *(uint2*)(uA0h + c * UPH + jq) = *(uint2*)hh;
        }
    }
    __syncthreads();

    float mi0 = 0.f, mi1 = 0.f;
    float ax = 0.f, ay = 0.f, az = 0.f;

    for (int t = 0; t < 8; t++) {
        __half* uCur  = (t & 1) ? uA1h : uA0h;
        __half* uNext = (t & 1) ? uA0h : uA1h;

        // ======== Phase P1: GEMM B (+ m_self(t0), x-accum(t-1), geo prefetch) ========
        const bool pf = (tid < 128) && (t + 1 < 8);
        float pd2 = 0.f, pa = 0.f;
        if (pf) {
            int jn = (t + 1) * 128 + tid;
            float dx = xi0 - x[jn * 3 + 0];
            float dy = xi1 - x[jn * 3 + 1];
            float dz = xi2 - x[jn * 3 + 2];
            pd2 = dx * dx + dy * dy + dz * dz;
            pa = a[i * M_NODES + jn];
        }
        if (t == 0 && tid < 64) {
            float accd = be2s[tid];
#pragma unroll 8
            for (int c = 0; c < 64; c++)
                accd += u_self[c] * __half2float(W2h[tid + c * 64]);
            m_self[tid] = silu_f(accd);
        }
        if (t > 0 && tid < 128) {
            int jg = (t - 1) * 128 + tid;
            float s = bx2v + redxp[tid] + redxp[132 + tid]
                           + redxp[264 + tid] + redxp[396 + tid];
            float dx = xi0 - x[jg * 3 + 0];
            float dy = xi1 - x[jg * 3 + 1];
            float dz = xi2 - x[jg * 3 + 2];
            ax += dx * s; ay += dy * s; az += dz * s;
        }

        gemmB(W2h, uCur, mTh, be2s, mi0, mi1, kw, jw, lane);

        if (pf) {
            float* gn = sm + OFF_GEOA + ((t + 1) & 1) * 256;
            gn[tid] = pd2;
            gn[128 + tid] = pa;
        }
        __syncthreads();

        // ======== Phase P2: GEMM C + phase A(t+1) ========
        gemmC(Wx1h, mTh, bx1s, wx2s, redxp, kw, jw, lane);

        if (t + 1 < 8) {
            const float* geoA = sm + OFF_GEOA + ((t + 1) & 1) * 256;
            const int j0 = (t + 1) * 128;
            const int jq = lane * 4;
#pragma unroll
            for (int p = 0; p < 8; p++) {
                int c = p * 8 + w;
                float4 pj = *(const float4*)&g_pe_jT[c * M_NODES + j0 + jq];
                float pc = peib[c], wa = w128s[c], wb = w129s[c];
                float4 dd = *(const float4*)&geoA[jq];
                float4 aa = *(const float4*)&geoA[128 + jq];
                __half hh[4];
                hh[0] = __float2half_rn(silu_f(pc + pj.x + dd.x * wa + aa.x * wb));
                hh[1] = __float2half_rn(silu_f(pc + pj.y + dd.y * wa + aa.y * wb));
                hh[2] = __float2half_rn(silu_f(pc + pj.z + dd.z * wa + aa.z * wb));
                hh[3] = __float2half_rn(silu_f(pc + pj.w + dd.w * wa + aa.w * wb));
                *(uint2*)(uNext + c * UPH + jq) = *(uint2*)hh;
            }
        }
        __syncthreads();
    }

    // x-accum for tile 7
    if (tid < 128) {
        int jg = 7 * 128 + tid;
        float s = bx2v + redxp[tid] + redxp[132 + tid]
                       + redxp[264 + tid] + redxp[396 + tid];
        float dx = xi0 - x[jg * 3 + 0];
        float dy = xi1 - x[jg * 3 + 1];
        float dz = xi2 - x[jg * 3 + 2];
        ax += dx * s; ay += dy * s; az += dz * s;
    }

    // ---- m_i reduction: combine lanes sharing the same k-row (xor 1,2) ----
    mi0 += __shfl_xor_sync(0xffffffff, mi0, 1);
    mi0 += __shfl_xor_sync(0xffffffff, mi0, 2);
    mi1 += __shfl_xor_sync(0xffffffff, mi1, 1);
    mi1 += __shfl_xor_sync(0xffffffff, mi1, 2);

    float* redm = sm + OFF_RED;           // [64][2]
    float* redx = sm + OFF_RED + 128;     // 384
    {
        const int q = lane >> 2, g = jw >> 6;
        if ((lane & 3) == 0) {
            redm[(kw + q) * 2 + g]     = mi0;
            redm[(kw + q + 8) * 2 + g] = mi1;
        }
    }
    if (tid < 128) { redx[tid] = ax; redx[128 + tid] = ay; redx[256 + tid] = az; }
    __syncthreads();

    float* mis = sm + OFF_GEOA;
    float* gs  = sm + OFF_GEOA + 64;
    if (tid < 64) {
        mis[tid] = redm[tid * 2] + redm[tid * 2 + 1] - m_self[tid];
    }
    if (tid >= 128 && tid < 131) {
        int comp = tid - 128;
        float s = 0.f;
        for (int q = 0; q < 128; q++) s += redx[comp * 128 + q];
        const float C = 1.0f / (float)(M_NODES - 1);
        out[i * 3 + comp] = x[i * 3 + comp] + C * s;
    }
    __syncthreads();

    // phi_h
    if (tid < 64) {
        float acc = bh1[tid];
        const float* hr = h + i * 64;
#pragma unroll 4
        for (int c = 0; c < 64; c++) acc += hr[c] * Wh1[c * 64 + tid];
#pragma unroll 4
        for (int c = 0; c < 64; c++) acc += mis[c] * Wh1[(64 + c) * 64 + tid];
        gs[tid] = silu_f(acc);
    }
    __syncthreads();
    if (tid < 64) {
        float acc = bh2[tid];
#pragma unroll 4
        for (int c = 0; c < 64; c++) acc += gs[c] * Wh2[c * 64 + tid];
        out[3 * M_NODES + i * 64 + tid] = acc;
    }
}

extern "C" void kernel_launch(void* const* d_in, const int* in_sizes, int n_in,
                              void* d_out, int out_size) {
    const float* x   = (const float*)d_in[0];
    const float* a   = (const float*)d_in[1];
    const float* h   = (const float*)d_in[2];
    const float* We1 = (const float*)d_in[3];
    const float* be1 = (const float*)d_in[4];
    const float* We2 = (const float*)d_in[5];
    const float* be2 = (const float*)d_in[6];
    const float* Wx1 = (const float*)d_in[7];
    const float* bx1 = (const float*)d_in[8];
    const float* Wx2 = (const float*)d_in[9];
    const float* bx2 = (const float*)d_in[10];
    const float* Wh1 = (const float*)d_in[11];
    const float* bh1 = (const float*)d_in[12];
    const float* Wh2 = (const float*)d_in[13];
    const float* bh2 = (const float*)d_in[14];
    float* out = (float*)d_out;

    cudaFuncSetAttribute(egnn_main, cudaFuncAttributeMaxDynamicSharedMemorySize, SMEM_BYTES);

    pe_kernel<<<(M_NODES * 64) / NTHREADS, NTHREADS>>>(h, We1);
    egnn_main<<<M_NODES, NTHREADS, SMEM_BYTES>>>(
        x, a, h, We1, be1, We2, be2, Wx1, bx1, Wx2, bx2,
        Wh1, bh1, Wh2, bh2, out);
}